// round 13
// baseline (speedup 1.0000x reference)
#include <cuda_runtime.h>
#include <cuda_bf16.h>
#include <stdint.h>
#include <math.h>

typedef unsigned int u32;
typedef unsigned long long u64;

// Problem constants
constexpr int B_   = 2;
constexpr int S_   = 2048;
constexpr int HID_ = 1024;
constexpr int NH_  = 16;
constexpr int DK_  = 64;
constexpr int M_   = B_ * S_;   // 4096

// ---------------------------------------------------------------------------
// Scratch (device globals; no allocation allowed)
// ---------------------------------------------------------------------------
__device__ float g_q  [B_ * NH_ * S_ * DK_];
__device__ float g_k  [B_ * NH_ * S_ * DK_];
__device__ float g_v  [B_ * NH_ * S_ * DK_];
__device__ float g_att[B_ * S_ * HID_];

// ---------------------------------------------------------------------------
// f32x2 packed helpers
// ---------------------------------------------------------------------------
__device__ __forceinline__ void fma2(u64& d, u64 a, u64 b) {
    asm("fma.rn.f32x2 %0, %1, %2, %0;" : "+l"(d) : "l"(a), "l"(b));
}
__device__ __forceinline__ u64 dup2(float x) {
    u64 r;
    asm("mov.b64 %0, {%1, %1};" : "=l"(r) : "r"(__float_as_uint(x)));
    return r;
}
__device__ __forceinline__ float2 upk2(u64 v) {
    u32 lo, hi;
    asm("mov.b64 {%0, %1}, %2;" : "=r"(lo), "=r"(hi) : "l"(v));
    return make_float2(__uint_as_float(lo), __uint_as_float(hi));
}

// ---------------------------------------------------------------------------
// FFMA2 SGEMM v3: C = A @ W^T + bias
// A [M,1024] row-major, W [N,1024] row-major.
// CTA tile 128m x 128n, BK=32, 256 threads, grid (8,32) = 256 CTAs.
// Thread tile: 4 m-pairs (m = ty*8 + 2*ip) x 8 n (n = tx*8 + j). acc = 32 u64.
// As2 staged transposed [k][m]  -> m-pairs are natural u64 loads.
// Ws2 staged transposed [k][n]  -> B duplicated in REGISTERS (mov.b64 {r,r}).
// MODE 0: C row-major [M,1024];  MODE 1: C in [B,NH,S,DK] layout.
// SCALEA: scale A rows by (1 + abias[row]) during staging.
// ---------------------------------------------------------------------------
constexpr int F2_LD   = 132;                     // smem row stride (floats)
constexpr int F2_SMEM = 2 * 32 * F2_LD * 4;      // 33792 bytes

template <int MODE, int SCALEA>
__global__ __launch_bounds__(256)
void sgemm_f2(const float* __restrict__ A, const float* __restrict__ W,
              const float* __restrict__ bias, const float* __restrict__ abias,
              float* __restrict__ C) {
    extern __shared__ float smf[];
    float* As2 = smf;                  // [32][F2_LD]  (k-major, m contiguous)
    float* Ws2 = smf + 32 * F2_LD;     // [32][F2_LD]  (k-major, n contiguous)

    const int tid = threadIdx.x;
    const int tx  = tid & 15;
    const int ty  = tid >> 4;
    const int m0  = blockIdx.y * 128;
    const int n0  = blockIdx.x * 128;

    u64 acc2[4][8];
#pragma unroll
    for (int ip = 0; ip < 4; ip++)
#pragma unroll
        for (int j = 0; j < 8; j++) acc2[ip][j] = 0ull;

    for (int kt = 0; kt < 32; kt++) {
        const int k0 = kt * 32;

        // gather global (A and W tiles: 128 rows x 32 k each)
        float4 ga[4], gw[4];
        float  fs[4];
#pragma unroll
        for (int it = 0; it < 4; it++) {
            int idx = tid + it * 256;          // 0..1023
            int r  = idx >> 3;                 // row 0..127
            int kg = idx & 7;                  // float4 group 0..7
            ga[it] = *(const float4*)&A[(size_t)(m0 + r) * 1024 + k0 + kg * 4];
            gw[it] = *(const float4*)&W[(size_t)(n0 + r) * 1024 + k0 + kg * 4];
            if (SCALEA) fs[it] = 1.0f + abias[m0 + r];
        }

        __syncthreads();
#pragma unroll
        for (int it = 0; it < 4; it++) {
            int idx = tid + it * 256;
            int r  = idx >> 3;
            int kg = idx & 7;
            float4 a = ga[it];
            if (SCALEA) { a.x *= fs[it]; a.y *= fs[it]; a.z *= fs[it]; a.w *= fs[it]; }
            As2[(kg * 4 + 0) * F2_LD + r] = a.x;
            As2[(kg * 4 + 1) * F2_LD + r] = a.y;
            As2[(kg * 4 + 2) * F2_LD + r] = a.z;
            As2[(kg * 4 + 3) * F2_LD + r] = a.w;
            float4 w = gw[it];
            Ws2[(kg * 4 + 0) * F2_LD + r] = w.x;
            Ws2[(kg * 4 + 1) * F2_LD + r] = w.y;
            Ws2[(kg * 4 + 2) * F2_LD + r] = w.z;
            Ws2[(kg * 4 + 3) * F2_LD + r] = w.w;
        }
        __syncthreads();

#pragma unroll 4
        for (int kk = 0; kk < 32; kk++) {
            // A: 4 m-pairs (8 consecutive m) as u64
            ulonglong2 aq0 = *(const ulonglong2*)&As2[kk * F2_LD + ty * 8];
            ulonglong2 aq1 = *(const ulonglong2*)&As2[kk * F2_LD + ty * 8 + 4];
            u64 a2[4];
            a2[0] = aq0.x; a2[1] = aq0.y; a2[2] = aq1.x; a2[3] = aq1.y;
            // B: 8 n values, duplicated into u64 in registers
            float4 b0 = *(const float4*)&Ws2[kk * F2_LD + tx * 8];
            float4 b1 = *(const float4*)&Ws2[kk * F2_LD + tx * 8 + 4];
            u64 b2[8];
            b2[0] = dup2(b0.x); b2[1] = dup2(b0.y);
            b2[2] = dup2(b0.z); b2[3] = dup2(b0.w);
            b2[4] = dup2(b1.x); b2[5] = dup2(b1.y);
            b2[6] = dup2(b1.z); b2[7] = dup2(b1.w);
#pragma unroll
            for (int ip = 0; ip < 4; ip++)
#pragma unroll
                for (int j = 0; j < 8; j++)
                    fma2(acc2[ip][j], a2[ip], b2[j]);
        }
    }

    // epilogue
    const int n = n0 + tx * 8;
    float4 bv0 = *(const float4*)&bias[n];
    float4 bv1 = *(const float4*)&bias[n + 4];
#pragma unroll
    for (int ip = 0; ip < 4; ip++) {
        const int m = m0 + ty * 8 + 2 * ip;   // even row; odd = m+1
        float4 lo0, lo1, hi0, hi1;
        float2 p;
        p = upk2(acc2[ip][0]); lo0.x = p.x; hi0.x = p.y;
        p = upk2(acc2[ip][1]); lo0.y = p.x; hi0.y = p.y;
        p = upk2(acc2[ip][2]); lo0.z = p.x; hi0.z = p.y;
        p = upk2(acc2[ip][3]); lo0.w = p.x; hi0.w = p.y;
        p = upk2(acc2[ip][4]); lo1.x = p.x; hi1.x = p.y;
        p = upk2(acc2[ip][5]); lo1.y = p.x; hi1.y = p.y;
        p = upk2(acc2[ip][6]); lo1.z = p.x; hi1.z = p.y;
        p = upk2(acc2[ip][7]); lo1.w = p.x; hi1.w = p.y;
        lo0.x += bv0.x; lo0.y += bv0.y; lo0.z += bv0.z; lo0.w += bv0.w;
        hi0.x += bv0.x; hi0.y += bv0.y; hi0.z += bv0.z; hi0.w += bv0.w;
        lo1.x += bv1.x; lo1.y += bv1.y; lo1.z += bv1.z; lo1.w += bv1.w;
        hi1.x += bv1.x; hi1.y += bv1.y; hi1.z += bv1.z; hi1.w += bv1.w;
        if (MODE == 0) {
            *(float4*)&C[(size_t)m * 1024 + n]           = lo0;
            *(float4*)&C[(size_t)m * 1024 + n + 4]       = lo1;
            *(float4*)&C[(size_t)(m + 1) * 1024 + n]     = hi0;
            *(float4*)&C[(size_t)(m + 1) * 1024 + n + 4] = hi1;
        } else {
            const int h = n >> 6;
            const int d = n & 63;
            const int bb0 = m >> 11, ss0 = m & (S_ - 1);
            const int bb1 = (m + 1) >> 11, ss1 = (m + 1) & (S_ - 1);
            size_t base0 = ((size_t)(bb0 * NH_ + h) * S_ + ss0) * DK_ + d;
            size_t base1 = ((size_t)(bb1 * NH_ + h) * S_ + ss1) * DK_ + d;
            *(float4*)&C[base0]     = lo0;
            *(float4*)&C[base0 + 4] = lo1;
            *(float4*)&C[base1]     = hi0;
            *(float4*)&C[base1 + 4] = hi1;
        }
    }
}

// ---------------------------------------------------------------------------
// Fused flash attention (R10 proven version, byte-identical)
// ---------------------------------------------------------------------------
constexpr int FLASH_SMEM = (16576 + 64) * 4;   // 66560 bytes

__global__ __launch_bounds__(256)
void flash_kernel(const float* __restrict__ Q, const float* __restrict__ K,
                  const float* __restrict__ V, const int* __restrict__ mask,
                  float* __restrict__ out) {
    extern __shared__ float sm[];
    float* Qs    = sm;            // [d][q]
    float* Ks    = sm + 4096;     // [d][k]
    float* Vs    = sm + 8192;     // [k][d]
    float* ST    = sm + 12288;    // [k][q], stride 65
    float* alf   = sm + 16448;
    float* linv  = sm + 16512;
    int*   msk   = (int*)(sm + 16576);

    const int tid = threadIdx.x;
    const int tx  = tid & 15;
    const int ty  = tid >> 4;
    const int b   = blockIdx.z;
    const int h   = blockIdx.y;
    const int q0  = blockIdx.x * 64;
    const int bh  = b * NH_ + h;

    const float* Qb = Q + (size_t)bh * S_ * DK_;
    const float* Kb = K + (size_t)bh * S_ * DK_;
    const float* Vb = V + (size_t)bh * S_ * DK_;
    const int*   mb = mask + b * S_;

#pragma unroll
    for (int i = 0; i < 4; i++) {
        int f = tid + i * 256;
        int r = f >> 4;
        int c = (f & 15) * 4;
        float4 qv = *(const float4*)(Qb + (size_t)(q0 + r) * DK_ + c);
        Qs[(c + 0) * 64 + r] = qv.x;
        Qs[(c + 1) * 64 + r] = qv.y;
        Qs[(c + 2) * 64 + r] = qv.z;
        Qs[(c + 3) * 64 + r] = qv.w;
    }

    float Ob[4][4];
#pragma unroll
    for (int i = 0; i < 4; i++)
#pragma unroll
        for (int j = 0; j < 4; j++) Ob[i][j] = 0.0f;

    const int r    = ty * 4 + (tx & 3);
    const int k0s  = (tx >> 2) * 16;
    float m_row = -1.0e30f;
    float l_row = 0.0f;

    for (int kt = 0; kt < S_; kt += 64) {
        __syncthreads();

#pragma unroll
        for (int i = 0; i < 4; i++) {
            int f = tid + i * 256;
            int rr = f >> 4;
            int cc = (f & 15) * 4;
            float4 kv = *(const float4*)(Kb + (size_t)(kt + rr) * DK_ + cc);
            Ks[(cc + 0) * 64 + rr] = kv.x;
            Ks[(cc + 1) * 64 + rr] = kv.y;
            Ks[(cc + 2) * 64 + rr] = kv.z;
            Ks[(cc + 3) * 64 + rr] = kv.w;
            float4 vv = *(const float4*)(Vb + (size_t)(kt + rr) * DK_ + cc);
            *(float4*)&Vs[rr * 64 + cc] = vv;
        }
        if (tid < 64) msk[tid] = mb[kt + tid];
        __syncthreads();

        float sacc[4][4];
#pragma unroll
        for (int i = 0; i < 4; i++)
#pragma unroll
            for (int j = 0; j < 4; j++) sacc[i][j] = 0.0f;

#pragma unroll 8
        for (int d = 0; d < DK_; d++) {
            float4 a  = *(const float4*)&Qs[d * 64 + ty * 4];
            float4 bb = *(const float4*)&Ks[d * 64 + tx * 4];
            float af[4] = {a.x, a.y, a.z, a.w};
            float bf[4] = {bb.x, bb.y, bb.z, bb.w};
#pragma unroll
            for (int i = 0; i < 4; i++)
#pragma unroll
                for (int j = 0; j < 4; j++) sacc[i][j] += af[i] * bf[j];
        }

#pragma unroll
        for (int j = 0; j < 4; j++) {
            const int mk = msk[tx * 4 + j];
#pragma unroll
            for (int i = 0; i < 4; i++) {
                ST[(tx * 4 + j) * 65 + ty * 4 + i] =
                    mk ? sacc[i][j] * 0.125f : -10000.0f;
            }
        }
        __syncthreads();

        float tm = -1.0e30f;
#pragma unroll
        for (int t = 0; t < 16; t++)
            tm = fmaxf(tm, ST[(k0s + t) * 65 + r]);
        tm = fmaxf(tm, __shfl_xor_sync(0xFFFFFFFFu, tm, 4));
        tm = fmaxf(tm, __shfl_xor_sync(0xFFFFFFFFu, tm, 8));

        const float m_new = fmaxf(m_row, tm);
        const float al    = __expf(m_row - m_new);
        float sum = 0.0f;
#pragma unroll
        for (int t = 0; t < 16; t++) {
            float e = __expf(ST[(k0s + t) * 65 + r] - m_new);
            ST[(k0s + t) * 65 + r] = e;
            sum += e;
        }
        sum += __shfl_xor_sync(0xFFFFFFFFu, sum, 4);
        sum += __shfl_xor_sync(0xFFFFFFFFu, sum, 8);
        l_row = l_row * al + sum;
        m_row = m_new;
        if ((tx >> 2) == 0) alf[r] = al;
        __syncthreads();

        float a0 = alf[ty * 4 + 0];
        float a1 = alf[ty * 4 + 1];
        float a2 = alf[ty * 4 + 2];
        float a3 = alf[ty * 4 + 3];
#pragma unroll
        for (int j = 0; j < 4; j++) {
            Ob[0][j] *= a0; Ob[1][j] *= a1; Ob[2][j] *= a2; Ob[3][j] *= a3;
        }

#pragma unroll 4
        for (int kk = 0; kk < 64; kk++) {
            float p0 = ST[kk * 65 + ty * 4 + 0];
            float p1 = ST[kk * 65 + ty * 4 + 1];
            float p2 = ST[kk * 65 + ty * 4 + 2];
            float p3 = ST[kk * 65 + ty * 4 + 3];
            float4 bv = *(const float4*)&Vs[kk * 64 + tx * 4];
            float bf[4] = {bv.x, bv.y, bv.z, bv.w};
#pragma unroll
            for (int j = 0; j < 4; j++) {
                Ob[0][j] += p0 * bf[j];
                Ob[1][j] += p1 * bf[j];
                Ob[2][j] += p2 * bf[j];
                Ob[3][j] += p3 * bf[j];
            }
        }
    }

    if ((tx >> 2) == 0) linv[r] = 1.0f / l_row;
    __syncthreads();

#pragma unroll
    for (int i = 0; i < 4; i++) {
        const float rv = linv[ty * 4 + i];
        float4 o;
        o.x = Ob[i][0] * rv; o.y = Ob[i][1] * rv;
        o.z = Ob[i][2] * rv; o.w = Ob[i][3] * rv;
        *(float4*)(out + ((size_t)b * S_ + q0 + ty * 4 + i) * HID_ + h * DK_ + tx * 4) = o;
    }
}

// ---------------------------------------------------------------------------
// launch
// ---------------------------------------------------------------------------
extern "C" void kernel_launch(void* const* d_in, const int* in_sizes, int n_in,
                              void* d_out, int out_size) {
    const float* query = (const float*)d_in[0];
    const float* key   = (const float*)d_in[1];
    const float* value = (const float*)d_in[2];
    const float* bias  = (const float*)d_in[3];
    const int*   mask  = (const int*)  d_in[4];
    const float* wq    = (const float*)d_in[5];
    const float* bq    = (const float*)d_in[6];
    const float* wk    = (const float*)d_in[7];
    const float* bk    = (const float*)d_in[8];
    const float* wv    = (const float*)d_in[9];
    const float* bv    = (const float*)d_in[10];
    const float* wo    = (const float*)d_in[11];
    const float* bo    = (const float*)d_in[12];
    float* out = (float*)d_out;

    float *p_q, *p_k, *p_v, *p_att;
    cudaGetSymbolAddress((void**)&p_q,   g_q);
    cudaGetSymbolAddress((void**)&p_k,   g_k);
    cudaGetSymbolAddress((void**)&p_v,   g_v);
    cudaGetSymbolAddress((void**)&p_att, g_att);

    cudaFuncSetAttribute(sgemm_f2<0, 0>, cudaFuncAttributeMaxDynamicSharedMemorySize, F2_SMEM);
    cudaFuncSetAttribute(sgemm_f2<1, 0>, cudaFuncAttributeMaxDynamicSharedMemorySize, F2_SMEM);
    cudaFuncSetAttribute(sgemm_f2<1, 1>, cudaFuncAttributeMaxDynamicSharedMemorySize, F2_SMEM);
    cudaFuncSetAttribute(flash_kernel,   cudaFuncAttributeMaxDynamicSharedMemorySize, FLASH_SMEM);

    dim3 ggrid(1024 / 128, M_ / 128);    // (8, 32) = 256 CTAs

    // 1) projections (K/V scaled by 1+bias during staging), write [B,NH,S,DK]
    sgemm_f2<1, 0><<<ggrid, 256, F2_SMEM>>>(query, wq, bq, nullptr, p_q);
    sgemm_f2<1, 1><<<ggrid, 256, F2_SMEM>>>(key,   wk, bk, bias,    p_k);
    sgemm_f2<1, 1><<<ggrid, 256, F2_SMEM>>>(value, wv, bv, bias,    p_v);

    // 2) fused flash attention
    {
        dim3 grid(S_ / 64, NH_, B_);     // (32, 16, 2)
        flash_kernel<<<grid, 256, FLASH_SMEM>>>(p_q, p_k, p_v, mask, p_att);
    }

    // 3) output projection (row-major out)
    sgemm_f2<0, 0><<<ggrid, 256, F2_SMEM>>>(p_att, wo, bo, nullptr, out);
}

// round 14
// speedup vs baseline: 1.6400x; 1.6400x over previous
#include <cuda_runtime.h>
#include <cuda_bf16.h>
#include <stdint.h>
#include <math.h>

// Problem constants
constexpr int B_   = 2;
constexpr int S_   = 2048;
constexpr int HID_ = 1024;
constexpr int NH_  = 16;
constexpr int DK_  = 64;
constexpr int M_   = B_ * S_;   // 4096

// ---------------------------------------------------------------------------
// Scratch (device globals; no allocation allowed)
// ---------------------------------------------------------------------------
__device__ float g_q  [B_ * NH_ * S_ * DK_];
__device__ float g_k  [B_ * NH_ * S_ * DK_];
__device__ float g_v  [B_ * NH_ * S_ * DK_];
__device__ float g_att[B_ * S_ * HID_];

// ---------------------------------------------------------------------------
// SGEMM (R3-proven scalar kernel + fused A-row scaling): C = A @ W^T + bias
// MODE 0: C row-major [M,1024];  MODE 1: C in [B,NH,S,DK] layout.
// SCALEA: scale A row m by (1 + abias[m]) during staging (K/V prep fusion).
// ---------------------------------------------------------------------------
template <int MODE, int SCALEA>
__global__ __launch_bounds__(256)
void sgemm_kernel(const float* __restrict__ A,
                  const float* __restrict__ W,
                  const float* __restrict__ bias,
                  const float* __restrict__ abias,
                  float* __restrict__ C) {
    constexpr int K = 1024;
    constexpr int N = 1024;

    __shared__ float As[8][128];
    __shared__ float Bs[8][128];

    const int tid = threadIdx.x;
    const int tx  = tid % 16;
    const int ty  = tid / 16;
    const int m0  = blockIdx.y * 128;
    const int n0  = blockIdx.x * 128;

    const int lrow = tid >> 1;
    const int lcol = (tid & 1) * 4;

    const float fs = SCALEA ? (1.0f + abias[m0 + lrow]) : 1.0f;

    float acc[8][8];
#pragma unroll
    for (int i = 0; i < 8; i++)
#pragma unroll
        for (int j = 0; j < 8; j++) acc[i][j] = 0.0f;

    const float* Aptr = A + (m0 + lrow) * K + lcol;
    const float* Wptr = W + (n0 + lrow) * K + lcol;

    for (int k0 = 0; k0 < K; k0 += 8) {
        float4 a  = *(const float4*)(Aptr + k0);
        float4 bw = *(const float4*)(Wptr + k0);
        if (SCALEA) { a.x *= fs; a.y *= fs; a.z *= fs; a.w *= fs; }
        __syncthreads();
        As[lcol + 0][lrow] = a.x;  As[lcol + 1][lrow] = a.y;
        As[lcol + 2][lrow] = a.z;  As[lcol + 3][lrow] = a.w;
        Bs[lcol + 0][lrow] = bw.x; Bs[lcol + 1][lrow] = bw.y;
        Bs[lcol + 2][lrow] = bw.z; Bs[lcol + 3][lrow] = bw.w;
        __syncthreads();

#pragma unroll
        for (int kk = 0; kk < 8; kk++) {
            float af[8], bf[8];
#pragma unroll
            for (int i = 0; i < 8; i++) af[i] = As[kk][ty * 8 + i];
#pragma unroll
            for (int j = 0; j < 8; j++) bf[j] = Bs[kk][tx * 8 + j];
#pragma unroll
            for (int i = 0; i < 8; i++)
#pragma unroll
                for (int j = 0; j < 8; j++) acc[i][j] += af[i] * bf[j];
        }
    }

#pragma unroll
    for (int i = 0; i < 8; i++) {
        int m = m0 + ty * 8 + i;
#pragma unroll
        for (int j = 0; j < 8; j++) {
            int n = n0 + tx * 8 + j;
            float val = acc[i][j] + bias[n];
            if (MODE == 0) {
                C[m * N + n] = val;
            } else {
                int b = m >> 11;
                int s = m & (S_ - 1);
                int h = n >> 6;
                int d = n & (DK_ - 1);
                C[((b * NH_ + h) * S_ + s) * DK_ + d] = val;
            }
        }
    }
}

// ---------------------------------------------------------------------------
// Flash attention v2: per (b,h), BQ=128 q-rows per CTA, k-tile 64, online
// softmax. 256 threads: tx 0..15, ty 0..15. Thread tiles 8q x 4k / 8q x 4d.
// smem floats:
//   Qs [64][128] @0       (d-major)
//   Ks [64][64]  @8192    (d-major)
//   Vs [64][64]  @12288   (k-major)
//   ST [128][68] @16384   (q-major scores/P)
//   alf[128] @25088  linv[128] @25216  msk[64] @25344
// ---------------------------------------------------------------------------
constexpr int FL2_FLOATS = 25408;
constexpr int FL2_SMEM   = FL2_FLOATS * 4;   // 101632 bytes

__global__ __launch_bounds__(256)
void flash2_kernel(const float* __restrict__ Q, const float* __restrict__ K,
                   const float* __restrict__ V, const int* __restrict__ mask,
                   float* __restrict__ out) {
    extern __shared__ float sm[];
    float* Qs   = sm;            // [d][q] stride 128
    float* Ks   = sm + 8192;     // [d][k] stride 64
    float* Vs   = sm + 12288;    // [k][d] stride 64
    float* ST   = sm + 16384;    // [q][k] stride 68
    float* alf  = sm + 25088;
    float* linv = sm + 25216;
    int*   msk  = (int*)(sm + 25344);

    const int tid = threadIdx.x;
    const int tx  = tid & 15;
    const int ty  = tid >> 4;
    const int b   = blockIdx.z;
    const int h   = blockIdx.y;
    const int q0  = blockIdx.x * 128;
    const int bh  = b * NH_ + h;

    const float* Qb = Q + (size_t)bh * S_ * DK_;
    const float* Kb = K + (size_t)bh * S_ * DK_;
    const float* Vb = V + (size_t)bh * S_ * DK_;
    const int*   mb = mask + b * S_;

    // load Q tile transposed into Qs[d][q] (128 rows x 64 d)
#pragma unroll
    for (int it = 0; it < 8; it++) {
        int f = tid + it * 256;          // 0..2047 float4 index
        int r = f >> 4;                  // q 0..127
        int c = (f & 15) * 4;            // d
        float4 qv = *(const float4*)&Qb[(size_t)(q0 + r) * DK_ + c];
        Qs[(c + 0) * 128 + r] = qv.x;
        Qs[(c + 1) * 128 + r] = qv.y;
        Qs[(c + 2) * 128 + r] = qv.z;
        Qs[(c + 3) * 128 + r] = qv.w;
    }

    float Ob[8][4];
#pragma unroll
    for (int i = 0; i < 8; i++)
#pragma unroll
        for (int j = 0; j < 4; j++) Ob[i][j] = 0.0f;

    const int r    = tid >> 1;       // softmax row 0..127
    const int half = tid & 1;        // 0/1: k-halves 0..31 / 32..63
    float m_row = -1.0e30f;
    float l_row = 0.0f;

    for (int kt = 0; kt < S_; kt += 64) {
        __syncthreads();   // prev PV done before overwriting Ks/Vs; ST reuse

        // stage K transposed [d][k], V direct [k][d]
#pragma unroll
        for (int it = 0; it < 4; it++) {
            int f = tid + it * 256;      // 0..1023
            int rr = f >> 4;             // k 0..63
            int cc = (f & 15) * 4;       // d
            float4 kv = *(const float4*)&Kb[(size_t)(kt + rr) * DK_ + cc];
            Ks[(cc + 0) * 64 + rr] = kv.x;
            Ks[(cc + 1) * 64 + rr] = kv.y;
            Ks[(cc + 2) * 64 + rr] = kv.z;
            Ks[(cc + 3) * 64 + rr] = kv.w;
            *(float4*)&Vs[rr * 64 + cc] = *(const float4*)&Vb[(size_t)(kt + rr) * DK_ + cc];
        }
        if (tid < 64) msk[tid] = mb[kt + tid];
        __syncthreads();

        // GEMM1: S[q][k], thread = 8q (ty*8+i) x 4k (tx*4+j)
        float sacc[8][4];
#pragma unroll
        for (int i = 0; i < 8; i++)
#pragma unroll
            for (int j = 0; j < 4; j++) sacc[i][j] = 0.0f;

#pragma unroll 8
        for (int d = 0; d < DK_; d++) {
            float4 a0 = *(const float4*)&Qs[d * 128 + ty * 8];
            float4 a1 = *(const float4*)&Qs[d * 128 + ty * 8 + 4];
            float4 bb = *(const float4*)&Ks[d * 64 + tx * 4];
            float af[8] = {a0.x, a0.y, a0.z, a0.w, a1.x, a1.y, a1.z, a1.w};
            float bf[4] = {bb.x, bb.y, bb.z, bb.w};
#pragma unroll
            for (int i = 0; i < 8; i++)
#pragma unroll
                for (int j = 0; j < 4; j++) sacc[i][j] += af[i] * bf[j];
        }

        // mask + scale, store ST[q][k] (float4 per q-row)
        {
            int mk0 = msk[tx * 4 + 0];
            int mk1 = msk[tx * 4 + 1];
            int mk2 = msk[tx * 4 + 2];
            int mk3 = msk[tx * 4 + 3];
#pragma unroll
            for (int i = 0; i < 8; i++) {
                float4 v;
                v.x = mk0 ? sacc[i][0] * 0.125f : -10000.0f;
                v.y = mk1 ? sacc[i][1] * 0.125f : -10000.0f;
                v.z = mk2 ? sacc[i][2] * 0.125f : -10000.0f;
                v.w = mk3 ? sacc[i][3] * 0.125f : -10000.0f;
                *(float4*)&ST[(ty * 8 + i) * 68 + tx * 4] = v;
            }
        }
        __syncthreads();

        // online softmax: 2 threads per row, 32 k each (contiguous)
        {
            float* row = ST + r * 68 + half * 32;
            float tm = -1.0e30f;
#pragma unroll
            for (int t4 = 0; t4 < 8; t4++) {
                float4 x = *(const float4*)&row[t4 * 4];
                tm = fmaxf(tm, fmaxf(fmaxf(x.x, x.y), fmaxf(x.z, x.w)));
            }
            tm = fmaxf(tm, __shfl_xor_sync(0xFFFFFFFFu, tm, 1));

            const float m_new = fmaxf(m_row, tm);
            const float al    = __expf(m_row - m_new);
            float sum = 0.0f;
#pragma unroll
            for (int t4 = 0; t4 < 8; t4++) {
                float4 x = *(const float4*)&row[t4 * 4];
                x.x = __expf(x.x - m_new);
                x.y = __expf(x.y - m_new);
                x.z = __expf(x.z - m_new);
                x.w = __expf(x.w - m_new);
                *(float4*)&row[t4 * 4] = x;
                sum += x.x + x.y + x.z + x.w;
            }
            sum += __shfl_xor_sync(0xFFFFFFFFu, sum, 1);
            l_row = l_row * al + sum;
            m_row = m_new;
            if (half == 0) alf[r] = al;
        }
        __syncthreads();

        // rescale O and accumulate P @ V: thread = 8q x 4d (d = tx*4+j)
#pragma unroll
        for (int i = 0; i < 8; i++) {
            const float al_i = alf[ty * 8 + i];
#pragma unroll
            for (int j = 0; j < 4; j++) Ob[i][j] *= al_i;
        }

#pragma unroll 4
        for (int kk = 0; kk < 64; kk++) {
            float4 bv = *(const float4*)&Vs[kk * 64 + tx * 4];
            float bf[4] = {bv.x, bv.y, bv.z, bv.w};
#pragma unroll
            for (int i = 0; i < 8; i++) {
                const float p = ST[(ty * 8 + i) * 68 + kk];
                Ob[i][0] += p * bf[0];
                Ob[i][1] += p * bf[1];
                Ob[i][2] += p * bf[2];
                Ob[i][3] += p * bf[3];
            }
        }
    }

    if (half == 0) linv[r] = 1.0f / l_row;
    __syncthreads();

    // normalize and write to [B,S,HID]
#pragma unroll
    for (int i = 0; i < 8; i++) {
        const float rv = linv[ty * 8 + i];
        float4 o;
        o.x = Ob[i][0] * rv; o.y = Ob[i][1] * rv;
        o.z = Ob[i][2] * rv; o.w = Ob[i][3] * rv;
        *(float4*)&out[((size_t)b * S_ + q0 + ty * 8 + i) * HID_ + h * DK_ + tx * 4] = o;
    }
}

// ---------------------------------------------------------------------------
// launch
// ---------------------------------------------------------------------------
extern "C" void kernel_launch(void* const* d_in, const int* in_sizes, int n_in,
                              void* d_out, int out_size) {
    const float* query = (const float*)d_in[0];
    const float* key   = (const float*)d_in[1];
    const float* value = (const float*)d_in[2];
    const float* bias  = (const float*)d_in[3];
    const int*   mask  = (const int*)  d_in[4];
    const float* wq    = (const float*)d_in[5];
    const float* bq    = (const float*)d_in[6];
    const float* wk    = (const float*)d_in[7];
    const float* bk    = (const float*)d_in[8];
    const float* wv    = (const float*)d_in[9];
    const float* bv    = (const float*)d_in[10];
    const float* wo    = (const float*)d_in[11];
    const float* bo    = (const float*)d_in[12];
    float* out = (float*)d_out;

    float *p_q, *p_k, *p_v, *p_att;
    cudaGetSymbolAddress((void**)&p_q,   g_q);
    cudaGetSymbolAddress((void**)&p_k,   g_k);
    cudaGetSymbolAddress((void**)&p_v,   g_v);
    cudaGetSymbolAddress((void**)&p_att, g_att);

    cudaFuncSetAttribute(flash2_kernel,
                         cudaFuncAttributeMaxDynamicSharedMemorySize, FL2_SMEM);

    dim3 ggrid(1024 / 128, M_ / 128);    // (8, 32)

    // 1) projections; K/V scaled by (1+bias) during A-staging
    sgemm_kernel<1, 0><<<ggrid, 256>>>(query, wq, bq, nullptr, p_q);
    sgemm_kernel<1, 1><<<ggrid, 256>>>(key,   wk, bk, bias,    p_k);
    sgemm_kernel<1, 1><<<ggrid, 256>>>(value, wv, bv, bias,    p_v);

    // 2) fused flash attention (BQ=128)
    {
        dim3 grid(S_ / 128, NH_, B_);    // (16, 16, 2)
        flash2_kernel<<<grid, 256, FL2_SMEM>>>(p_q, p_k, p_v, mask, p_att);
    }

    // 3) output projection (row-major out)
    sgemm_kernel<0, 0><<<ggrid, 256>>>(p_att, wo, bo, nullptr, out);
}

// round 16
// speedup vs baseline: 2.3134x; 1.4106x over previous
#include <cuda_runtime.h>
#include <cuda_bf16.h>
#include <stdint.h>
#include <math.h>

// Problem constants
constexpr int B_   = 2;
constexpr int S_   = 2048;
constexpr int HID_ = 1024;
constexpr int NH_  = 16;
constexpr int DK_  = 64;
constexpr int M_   = B_ * S_;   // 4096

// ---------------------------------------------------------------------------
// Scratch (device globals; no allocation allowed)
// ---------------------------------------------------------------------------
__device__ float g_q  [B_ * NH_ * S_ * DK_];
__device__ float g_k  [B_ * NH_ * S_ * DK_];   // compacted per (b,h): rows 0..nv-1
__device__ float g_v  [B_ * NH_ * S_ * DK_];   // compacted per (b,h)
__device__ float g_att[B_ * S_ * HID_];
__device__ int   g_cidx[B_ * S_];              // exclusive prefix sum of mask
__device__ int   g_cnt [B_];                   // valid count per batch

// ---------------------------------------------------------------------------
// 0) per-batch exclusive scan of mask -> compact positions + counts
//    grid (B_), 256 threads
// ---------------------------------------------------------------------------
__global__ void scan_kernel(const int* __restrict__ mask) {
    __shared__ int s[256];
    __shared__ int offs;
    const int b   = blockIdx.x;
    const int tid = threadIdx.x;
    if (tid == 0) offs = 0;
    __syncthreads();

    for (int chunk = 0; chunk < S_; chunk += 256) {
        const int v = (mask[b * S_ + chunk + tid] != 0) ? 1 : 0;
        const int base = offs;
        s[tid] = v;
        __syncthreads();
#pragma unroll
        for (int d = 1; d < 256; d <<= 1) {
            int t = (tid >= d) ? s[tid - d] : 0;
            __syncthreads();
            s[tid] += t;
            __syncthreads();
        }
        g_cidx[b * S_ + chunk + tid] = base + s[tid] - v;   // exclusive
        const int total = s[255];
        __syncthreads();
        if (tid == 0) offs = base + total;
        __syncthreads();
    }
    if (tid == 0) g_cnt[b] = offs;
}

// ---------------------------------------------------------------------------
// SGEMM: C = A @ W^T + bias.
// MODE 0: C row-major [M,1024]
// MODE 1: C in [B,NH,S,DK] layout (Q projection)
// MODE 2: compacted scatter — only rows with mask[m]!=0 are written, at
//         position cidx[m] within [B,NH,*,DK] (K/V projections)
// SCALEA: scale A row m by (1 + abias[m]) during staging.
// ---------------------------------------------------------------------------
template <int MODE, int SCALEA>
__global__ __launch_bounds__(256)
void sgemm_kernel(const float* __restrict__ A,
                  const float* __restrict__ W,
                  const float* __restrict__ bias,
                  const float* __restrict__ abias,
                  const int* __restrict__ mask,
                  const int* __restrict__ cidx,
                  float* __restrict__ C) {
    constexpr int K = 1024;
    constexpr int N = 1024;

    __shared__ float As[8][128];
    __shared__ float Bs[8][128];

    const int tid = threadIdx.x;
    const int tx  = tid % 16;
    const int ty  = tid / 16;
    const int m0  = blockIdx.y * 128;
    const int n0  = blockIdx.x * 128;

    const int lrow = tid >> 1;
    const int lcol = (tid & 1) * 4;

    const float fs = SCALEA ? (1.0f + abias[m0 + lrow]) : 1.0f;

    float acc[8][8];
#pragma unroll
    for (int i = 0; i < 8; i++)
#pragma unroll
        for (int j = 0; j < 8; j++) acc[i][j] = 0.0f;

    const float* Aptr = A + (m0 + lrow) * K + lcol;
    const float* Wptr = W + (n0 + lrow) * K + lcol;

    for (int k0 = 0; k0 < K; k0 += 8) {
        float4 a  = *(const float4*)(Aptr + k0);
        float4 bw = *(const float4*)(Wptr + k0);
        if (SCALEA) { a.x *= fs; a.y *= fs; a.z *= fs; a.w *= fs; }
        __syncthreads();
        As[lcol + 0][lrow] = a.x;  As[lcol + 1][lrow] = a.y;
        As[lcol + 2][lrow] = a.z;  As[lcol + 3][lrow] = a.w;
        Bs[lcol + 0][lrow] = bw.x; Bs[lcol + 1][lrow] = bw.y;
        Bs[lcol + 2][lrow] = bw.z; Bs[lcol + 3][lrow] = bw.w;
        __syncthreads();

#pragma unroll
        for (int kk = 0; kk < 8; kk++) {
            float af[8], bf[8];
#pragma unroll
            for (int i = 0; i < 8; i++) af[i] = As[kk][ty * 8 + i];
#pragma unroll
            for (int j = 0; j < 8; j++) bf[j] = Bs[kk][tx * 8 + j];
#pragma unroll
            for (int i = 0; i < 8; i++)
#pragma unroll
                for (int j = 0; j < 8; j++) acc[i][j] += af[i] * bf[j];
        }
    }

#pragma unroll
    for (int i = 0; i < 8; i++) {
        const int m = m0 + ty * 8 + i;
        int vld = 1, cpos = 0;
        if (MODE == 2) {
            vld  = mask[m];
            cpos = cidx[m];
        }
#pragma unroll
        for (int j = 0; j < 8; j++) {
            const int n = n0 + tx * 8 + j;
            const float val = acc[i][j] + bias[n];
            if (MODE == 0) {
                C[m * N + n] = val;
            } else if (MODE == 1) {
                const int b = m >> 11;
                const int s = m & (S_ - 1);
                const int h = n >> 6;
                const int d = n & (DK_ - 1);
                C[((b * NH_ + h) * S_ + s) * DK_ + d] = val;
            } else {
                if (vld) {
                    const int b = m >> 11;
                    const int h = n >> 6;
                    const int d = n & (DK_ - 1);
                    C[((b * NH_ + h) * S_ + cpos) * DK_ + d] = val;
                }
            }
        }
    }
}

// ---------------------------------------------------------------------------
// Flash attention v2c: per (b,h), BQ=128 q-rows per CTA, online softmax over
// COMPACTED keys (nv = g_cnt[b]); partial tail tile padded with -10000
// (exp underflows to exactly 0 -> bit-identical to reference arithmetic).
// 256 threads: tx 0..15, ty 0..15. Thread tiles 8q x 4k / 8q x 4d.
// smem floats:
//   Qs [64][128] @0   Ks [64][64] @8192   Vs [64][64] @12288
//   ST [128][68] @16384   alf[128] @25088  linv[128] @25216
// ---------------------------------------------------------------------------
constexpr int FL2_FLOATS = 25344;
constexpr int FL2_SMEM   = FL2_FLOATS * 4;   // 101376 bytes

__global__ __launch_bounds__(256)
void flash2_kernel(const float* __restrict__ Q, const float* __restrict__ K,
                   const float* __restrict__ V, const int* __restrict__ cnt,
                   float* __restrict__ out) {
    extern __shared__ float sm[];
    float* Qs   = sm;            // [d][q] stride 128
    float* Ks   = sm + 8192;     // [d][k] stride 64
    float* Vs   = sm + 12288;    // [k][d] stride 64
    float* ST   = sm + 16384;    // [q][k] stride 68
    float* alf  = sm + 25088;
    float* linv = sm + 25216;

    const int tid = threadIdx.x;
    const int tx  = tid & 15;
    const int ty  = tid >> 4;
    const int b   = blockIdx.z;
    const int h   = blockIdx.y;
    const int q0  = blockIdx.x * 128;
    const int bh  = b * NH_ + h;

    const float* Qb = Q + (size_t)bh * S_ * DK_;
    const float* Kb = K + (size_t)bh * S_ * DK_;
    const float* Vb = V + (size_t)bh * S_ * DK_;
    const int    nv = cnt[b];

    // load Q tile transposed into Qs[d][q] (128 rows x 64 d)
#pragma unroll
    for (int it = 0; it < 8; it++) {
        int f = tid + it * 256;
        int r = f >> 4;
        int c = (f & 15) * 4;
        float4 qv = *(const float4*)&Qb[(size_t)(q0 + r) * DK_ + c];
        Qs[(c + 0) * 128 + r] = qv.x;
        Qs[(c + 1) * 128 + r] = qv.y;
        Qs[(c + 2) * 128 + r] = qv.z;
        Qs[(c + 3) * 128 + r] = qv.w;
    }

    float Ob[8][4];
#pragma unroll
    for (int i = 0; i < 8; i++)
#pragma unroll
        for (int j = 0; j < 4; j++) Ob[i][j] = 0.0f;

    const int r    = tid >> 1;       // softmax row 0..127
    const int half = tid & 1;        // 0/1: k-halves
    float m_row = -1.0e30f;
    float l_row = 0.0f;

    for (int kt = 0; kt < nv; kt += 64) {
        __syncthreads();

        // stage K transposed [d][k], V direct [k][d] (rows beyond nv: garbage,
        // masked to -10000 below -> exp == 0 -> zero contribution)
#pragma unroll
        for (int it = 0; it < 4; it++) {
            int f = tid + it * 256;
            int rr = f >> 4;
            int cc = (f & 15) * 4;
            float4 kv = *(const float4*)&Kb[(size_t)(kt + rr) * DK_ + cc];
            Ks[(cc + 0) * 64 + rr] = kv.x;
            Ks[(cc + 1) * 64 + rr] = kv.y;
            Ks[(cc + 2) * 64 + rr] = kv.z;
            Ks[(cc + 3) * 64 + rr] = kv.w;
            *(float4*)&Vs[rr * 64 + cc] = *(const float4*)&Vb[(size_t)(kt + rr) * DK_ + cc];
        }
        __syncthreads();

        // GEMM1: S[q][k], thread = 8q (ty*8+i) x 4k (tx*4+j)
        float sacc[8][4];
#pragma unroll
        for (int i = 0; i < 8; i++)
#pragma unroll
            for (int j = 0; j < 4; j++) sacc[i][j] = 0.0f;

#pragma unroll 8
        for (int d = 0; d < DK_; d++) {
            float4 a0 = *(const float4*)&Qs[d * 128 + ty * 8];
            float4 a1 = *(const float4*)&Qs[d * 128 + ty * 8 + 4];
            float4 bb = *(const float4*)&Ks[d * 64 + tx * 4];
            float af[8] = {a0.x, a0.y, a0.z, a0.w, a1.x, a1.y, a1.z, a1.w};
            float bf[4] = {bb.x, bb.y, bb.z, bb.w};
#pragma unroll
            for (int i = 0; i < 8; i++)
#pragma unroll
                for (int j = 0; j < 4; j++) sacc[i][j] += af[i] * bf[j];
        }

        // tail masking + scale, store ST[q][k]
        {
            const int lim = nv - kt;          // valid k in this tile
            const int v0 = (tx * 4 + 0) < lim;
            const int v1 = (tx * 4 + 1) < lim;
            const int v2 = (tx * 4 + 2) < lim;
            const int v3 = (tx * 4 + 3) < lim;
#pragma unroll
            for (int i = 0; i < 8; i++) {
                float4 v;
                v.x = v0 ? sacc[i][0] * 0.125f : -10000.0f;
                v.y = v1 ? sacc[i][1] * 0.125f : -10000.0f;
                v.z = v2 ? sacc[i][2] * 0.125f : -10000.0f;
                v.w = v3 ? sacc[i][3] * 0.125f : -10000.0f;
                *(float4*)&ST[(ty * 8 + i) * 68 + tx * 4] = v;
            }
        }
        __syncthreads();

        // online softmax: 2 threads per row, 32 contiguous k each
        {
            float* row = ST + r * 68 + half * 32;
            float tm = -1.0e30f;
#pragma unroll
            for (int t4 = 0; t4 < 8; t4++) {
                float4 x = *(const float4*)&row[t4 * 4];
                tm = fmaxf(tm, fmaxf(fmaxf(x.x, x.y), fmaxf(x.z, x.w)));
            }
            tm = fmaxf(tm, __shfl_xor_sync(0xFFFFFFFFu, tm, 1));

            const float m_new = fmaxf(m_row, tm);
            const float al    = __expf(m_row - m_new);
            float sum = 0.0f;
#pragma unroll
            for (int t4 = 0; t4 < 8; t4++) {
                float4 x = *(const float4*)&row[t4 * 4];
                x.x = __expf(x.x - m_new);
                x.y = __expf(x.y - m_new);
                x.z = __expf(x.z - m_new);
                x.w = __expf(x.w - m_new);
                *(float4*)&row[t4 * 4] = x;
                sum += x.x + x.y + x.z + x.w;
            }
            sum += __shfl_xor_sync(0xFFFFFFFFu, sum, 1);
            l_row = l_row * al + sum;
            m_row = m_new;
            if (half == 0) alf[r] = al;
        }
        __syncthreads();

        // rescale O and accumulate P @ V
#pragma unroll
        for (int i = 0; i < 8; i++) {
            const float al_i = alf[ty * 8 + i];
#pragma unroll
            for (int j = 0; j < 4; j++) Ob[i][j] *= al_i;
        }

#pragma unroll 4
        for (int kk = 0; kk < 64; kk++) {
            float4 bv = *(const float4*)&Vs[kk * 64 + tx * 4];
            float bf[4] = {bv.x, bv.y, bv.z, bv.w};
#pragma unroll
            for (int i = 0; i < 8; i++) {
                const float p = ST[(ty * 8 + i) * 68 + kk];
                Ob[i][0] += p * bf[0];
                Ob[i][1] += p * bf[1];
                Ob[i][2] += p * bf[2];
                Ob[i][3] += p * bf[3];
            }
        }
    }

    if (half == 0) linv[r] = 1.0f / l_row;
    __syncthreads();

    // normalize and write to [B,S,HID]
#pragma unroll
    for (int i = 0; i < 8; i++) {
        const float rv = linv[ty * 8 + i];
        float4 o;
        o.x = Ob[i][0] * rv; o.y = Ob[i][1] * rv;
        o.z = Ob[i][2] * rv; o.w = Ob[i][3] * rv;
        *(float4*)&out[((size_t)b * S_ + q0 + ty * 8 + i) * HID_ + h * DK_ + tx * 4] = o;
    }
}

// ---------------------------------------------------------------------------
// launch
// ---------------------------------------------------------------------------
extern "C" void kernel_launch(void* const* d_in, const int* in_sizes, int n_in,
                              void* d_out, int out_size) {
    const float* query = (const float*)d_in[0];
    const float* key   = (const float*)d_in[1];
    const float* value = (const float*)d_in[2];
    const float* bias  = (const float*)d_in[3];
    const int*   mask  = (const int*)  d_in[4];
    const float* wq    = (const float*)d_in[5];
    const float* bq    = (const float*)d_in[6];
    const float* wk    = (const float*)d_in[7];
    const float* bk    = (const float*)d_in[8];
    const float* wv    = (const float*)d_in[9];
    const float* bv    = (const float*)d_in[10];
    const float* wo    = (const float*)d_in[11];
    const float* bo    = (const float*)d_in[12];
    float* out = (float*)d_out;

    float *p_q, *p_k, *p_v, *p_att;
    int *p_cidx, *p_cnt;
    cudaGetSymbolAddress((void**)&p_q,    g_q);
    cudaGetSymbolAddress((void**)&p_k,    g_k);
    cudaGetSymbolAddress((void**)&p_v,    g_v);
    cudaGetSymbolAddress((void**)&p_att,  g_att);
    cudaGetSymbolAddress((void**)&p_cidx, g_cidx);
    cudaGetSymbolAddress((void**)&p_cnt,  g_cnt);

    cudaFuncSetAttribute(flash2_kernel,
                         cudaFuncAttributeMaxDynamicSharedMemorySize, FL2_SMEM);

    // 0) mask scan -> compact indices + counts
    scan_kernel<<<B_, 256>>>(mask);

    dim3 ggrid(1024 / 128, M_ / 128);    // (8, 32)

    // 1) projections; K/V scaled by (1+bias) AND compact-scattered
    sgemm_kernel<1, 0><<<ggrid, 256>>>(query, wq, bq, nullptr, nullptr, nullptr, p_q);
    sgemm_kernel<2, 1><<<ggrid, 256>>>(key,   wk, bk, bias, mask, p_cidx, p_k);
    sgemm_kernel<2, 1><<<ggrid, 256>>>(value, wv, bv, bias, mask, p_cidx, p_v);

    // 2) fused flash attention over compacted keys
    {
        dim3 grid(S_ / 128, NH_, B_);    // (16, 16, 2)
        flash2_kernel<<<grid, 256, FL2_SMEM>>>(p_q, p_k, p_v, p_cnt, p_att);
    }

    // 3) output projection (row-major out)
    sgemm_kernel<0, 0><<<ggrid, 256>>>(p_att, wo, bo, nullptr, nullptr, nullptr, out);
}